// round 15
// baseline (speedup 1.0000x reference)
#include <cuda_runtime.h>
#include <cuda_bf16.h>
#include <cuda_fp16.h>
#include <cstdint>

#define BB 4
#define SS 2048
#define EE 1024
#define HH 16
#define DD 64
#define BSROWS (BB * SS)   // 8192

// Scratch (device globals; allocation-free per harness rules).
__device__ __half g_qh[BSROWS * EE];        // Q, fp16, pre-scaled by 1/32
__device__ __half g_kh[BSROWS * EE];        // K, fp16, row-major
__device__ __half g_vt[BSROWS * EE];        // V^T, fp16, [b][h][d][s]
__device__ __half g_ah[BSROWS * EE];        // attention out (fp16, feeds Wo)
__device__ __half g_xh[BSROWS * EE];
__device__ __half g_wqh[EE * EE];
__device__ __half g_wkh[EE * EE];
__device__ __half g_wvh[EE * EE];
__device__ __half g_woh[EE * EE];

// ---------------------------------------------------------------------------
// helpers
// ---------------------------------------------------------------------------
__device__ __forceinline__ uint32_t smem_u32(const void* p) {
    uint32_t a;
    asm("{ .reg .u64 t; cvta.to.shared.u64 t, %1; cvt.u32.u64 %0, t; }" : "=r"(a) : "l"(p));
    return a;
}
__device__ __forceinline__ void cp_async16(uint32_t dst, const void* src) {
    asm volatile("cp.async.ca.shared.global [%0], [%1], 16;" :: "r"(dst), "l"(src));
}
#define CP_COMMIT() asm volatile("cp.async.commit_group;" ::: "memory")
#define CP_WAIT(n)  asm volatile("cp.async.wait_group %0;" :: "n"(n) : "memory")

__device__ __forceinline__ void mma_f16(float* c, const uint32_t* a, const uint32_t* b) {
    asm volatile(
        "mma.sync.aligned.m16n8k16.row.col.f32.f16.f16.f32 "
        "{%0,%1,%2,%3}, {%4,%5,%6,%7}, {%8,%9}, {%0,%1,%2,%3};"
        : "+f"(c[0]), "+f"(c[1]), "+f"(c[2]), "+f"(c[3])
        : "r"(a[0]), "r"(a[1]), "r"(a[2]), "r"(a[3]), "r"(b[0]), "r"(b[1]));
}
__device__ __forceinline__ void ldsm_x4(uint32_t* r, uint32_t addr) {
    asm volatile("ldmatrix.sync.aligned.m8n8.x4.shared.b16 {%0,%1,%2,%3}, [%4];"
                 : "=r"(r[0]), "=r"(r[1]), "=r"(r[2]), "=r"(r[3]) : "r"(addr));
}

// ---------------------------------------------------------------------------
// fused prep: fp32 -> fp16 for x + 4 weights in ONE launch
// ---------------------------------------------------------------------------
__global__ void prep_all(const float* __restrict__ x,  const float* __restrict__ wq,
                         const float* __restrict__ wk, const float* __restrict__ wv,
                         const float* __restrict__ wo,
                         __half* xh, __half* wqh, __half* wkh, __half* wvh, __half* woh,
                         int xn4, int wn4)
{
    int i = blockIdx.x * blockDim.x + threadIdx.x;
    if (i >= xn4 + 4 * wn4) return;
    const float* s; __half* d; int j;
    if (i < xn4) { s = x; d = xh; j = i; }
    else {
        int t = i - xn4, sel = t / wn4; j = t - sel * wn4;
        s = (sel == 0) ? wq : (sel == 1) ? wk : (sel == 2) ? wv : wo;
        d = (sel == 0) ? wqh : (sel == 1) ? wkh : (sel == 2) ? wvh : woh;
    }
    float4 a = ((const float4*)s)[j];
    __half2* dd = (__half2*)d + 2 * j;
    dd[0] = __floats2half2_rn(a.x, a.y);
    dd[1] = __floats2half2_rn(a.z, a.w);
}

// ---------------------------------------------------------------------------
// fp16 mma.sync GEMM (R14 verbatim): CTA 128x256, 8 warps (2M x 4N),
// warp tile 64x64, BK=64, 2-stage cp.async, ldmatrix fragments.
// ---------------------------------------------------------------------------
#define HST 72
#define ROWB (HST * 2)
#define GA_H (128 * HST)
#define GB_H (256 * HST)
#define GSTG_B ((GA_H + GB_H) * 2)
#define GEMM_SMEM (2 * GSTG_B)       // 110592 B
#define NCH 16

__device__ __forceinline__ void gemm_body_h(
    const __half* __restrict__ A, const __half* __restrict__ W,
    const float* __restrict__ bias, void* __restrict__ Cv,
    int brow, int bcol, uint32_t smb, int mode)
{
    const int t    = threadIdx.x;
    const int lane = t & 31;
    const int w    = t >> 5;
    const int wm   = (w & 1) * 64;
    const int wn   = (w >> 1) * 64;
    const int g    = lane >> 2;
    const int tg   = lane & 3;

    const int la  = lane & 7;
    const int lb8 = ((lane >> 3) & 1) * 8;
    const int lq8 = (lane >> 4) * 8;
    const uint32_t aoff = (uint32_t)((wm + la + lb8) * HST + lq8) * 2;
    const uint32_t boff = (uint32_t)((wn + la + lq8) * HST + lb8) * 2;

    const int sr = t >> 1;
    const int sc = (t & 1) * 32;
    const __half* Ag = A + (long)(brow + sr) * EE + sc;
    const __half* Bg = W + (long)(bcol + t) * EE;
    const uint32_t sdA = smb + (sr * HST + sc) * 2;
    const uint32_t sdB = smb + GA_H * 2 + t * ROWB;

    float acc[4][8][4];
#pragma unroll
    for (int i = 0; i < 4; i++)
#pragma unroll
        for (int j = 0; j < 8; j++)
#pragma unroll
            for (int r = 0; r < 4; r++) acc[i][j][r] = 0.f;

#pragma unroll
    for (int j = 0; j < 4; j++) cp_async16(sdA + j * 16, Ag + j * 8);
#pragma unroll
    for (int j = 0; j < 8; j++) cp_async16(sdB + j * 16, Bg + j * 8);
    CP_COMMIT();

    for (int kc = 0; kc < NCH; kc++) {
        const int cur = kc & 1, nxt = cur ^ 1;

        if (kc + 1 < NCH) {
            const int k0 = (kc + 1) * 64;
            const uint32_t bofs = nxt * GSTG_B;
#pragma unroll
            for (int j = 0; j < 4; j++) cp_async16(sdA + bofs + j * 16, Ag + k0 + j * 8);
#pragma unroll
            for (int j = 0; j < 8; j++) cp_async16(sdB + bofs + j * 16, Bg + k0 + j * 8);
            CP_COMMIT();
            CP_WAIT(1);
        } else {
            CP_WAIT(0);
        }
        __syncthreads();

        const uint32_t stA = smb + cur * GSTG_B;
        const uint32_t stB = stA + GA_H * 2;

#pragma unroll
        for (int ks = 0; ks < 4; ks++) {
            uint32_t af[4][4], bf[8][2];
#pragma unroll
            for (int mt = 0; mt < 4; mt++)
                ldsm_x4(af[mt], stA + aoff + mt * 16 * ROWB + ks * 32);
#pragma unroll
            for (int p = 0; p < 4; p++) {
                uint32_t t4[4];
                ldsm_x4(t4, stB + boff + p * 16 * ROWB + ks * 32);
                bf[2 * p][0] = t4[0]; bf[2 * p][1] = t4[1];
                bf[2 * p + 1][0] = t4[2]; bf[2 * p + 1][1] = t4[3];
            }
#pragma unroll
            for (int mt = 0; mt < 4; mt++)
#pragma unroll
                for (int nt = 0; nt < 8; nt++)
                    mma_f16(acc[mt][nt], af[mt], bf[nt]);
        }
        __syncthreads();
    }

    if (mode == 0) {
        float* C = (float*)Cv;
#pragma unroll
        for (int mt = 0; mt < 4; mt++)
#pragma unroll
            for (int nt = 0; nt < 8; nt++) {
                const int row = brow + wm + mt * 16 + g;
                const int col = bcol + wn + nt * 8 + 2 * tg;
                float b0 = bias ? bias[col] : 0.f;
                float b1 = bias ? bias[col + 1] : 0.f;
                *(float2*)(C + (long)row * EE + col) =
                    make_float2(acc[mt][nt][0] + b0, acc[mt][nt][1] + b1);
                *(float2*)(C + (long)(row + 8) * EE + col) =
                    make_float2(acc[mt][nt][2] + b0, acc[mt][nt][3] + b1);
            }
    } else if (mode == 3) {          // V^T: [b][h][d][s]
        __half* C = (__half*)Cv;
#pragma unroll
        for (int mt = 0; mt < 4; mt++)
#pragma unroll
            for (int nt = 0; nt < 8; nt++) {
                const int row = brow + wm + mt * 16 + g;
                const int col = bcol + wn + nt * 8 + 2 * tg;
                const int bi = row >> 11, s = row & (SS - 1);
                const int h = col >> 6, d = col & 63;
                const long base = ((long)(bi * HH + h) * DD + d) * SS + s;
                C[base]          = __float2half_rn(acc[mt][nt][0]);
                C[base + SS]     = __float2half_rn(acc[mt][nt][1]);
                C[base + 8]      = __float2half_rn(acc[mt][nt][2]);
                C[base + SS + 8] = __float2half_rn(acc[mt][nt][3]);
            }
    } else {                         // fp16 row-major (Q scaled / K)
        __half* C = (__half*)Cv;
        const float sc2 = (mode == 1) ? 0.03125f : 1.0f;
#pragma unroll
        for (int mt = 0; mt < 4; mt++)
#pragma unroll
            for (int nt = 0; nt < 8; nt++) {
                const int row = brow + wm + mt * 16 + g;
                const int col = bcol + wn + nt * 8 + 2 * tg;
                *(__half2*)(C + (long)row * EE + col) =
                    __floats2half2_rn(acc[mt][nt][0] * sc2, acc[mt][nt][1] * sc2);
                *(__half2*)(C + (long)(row + 8) * EE + col) =
                    __floats2half2_rn(acc[mt][nt][2] * sc2, acc[mt][nt][3] * sc2);
            }
    }
}

__global__ void __launch_bounds__(256)
gemm_qkv_h(const __half* __restrict__ A,
           const __half* __restrict__ Wq, const __half* __restrict__ Wk,
           const __half* __restrict__ Wv,
           __half* __restrict__ Cq, __half* __restrict__ Ck, __half* __restrict__ Cv)
{
    extern __shared__ uint32_t smw[];
    const int sel  = blockIdx.x >> 2;
    const int bcol = (blockIdx.x & 3) * 256;
    const int brow = blockIdx.y * 128;
    const __half* W = (sel == 0) ? Wq : (sel == 1) ? Wk : Wv;
    void*         C = (sel == 0) ? (void*)Cq : (sel == 1) ? (void*)Ck : (void*)Cv;
    gemm_body_h(A, W, nullptr, C, brow, bcol, smem_u32(smw), sel + 1);
}

__global__ void __launch_bounds__(256)
gemm_h(const __half* __restrict__ A, const __half* __restrict__ W,
       const float* __restrict__ bias, float* __restrict__ C)
{
    extern __shared__ uint32_t smw[];
    gemm_body_h(A, W, bias, C, blockIdx.y * 128, blockIdx.x * 256,
                smem_u32(smw), 0);
}

// ---------------------------------------------------------------------------
// fp16 flash attention, CTA = 256 q-rows, 8 warps x 32 rows (2 m16 blocks).
// K/V fragments loaded once per ks, reused across both m-blocks.
// ---------------------------------------------------------------------------
#define FH 72                                // halves per smem row
#define KVH (64 * FH)                        // halves per K (or Vt) tile
#define KVBUF_H (2 * KVH)                    // halves per stage (18432)
#define NEG_BIG (-1e30f)
#define FLASH_SMEMH (2 * KVBUF_H + 8 * 32 * FH)   // 55296 halves = 110592 B

__global__ void __launch_bounds__(256, 1)
flash_h(const __half* __restrict__ Qg, const __half* __restrict__ Kg,
        const __half* __restrict__ Vtg, __half* __restrict__ Og)
{
    extern __shared__ __half hsm[];
    __half* Ph = hsm + 2 * KVBUF_H;

    const uint32_t smb = smem_u32(hsm);
    const int tid = threadIdx.x;
    const int w = tid >> 5, lane = tid & 31;
    const int g = lane >> 2, tg = lane & 3;
    const int qt = gridDim.x - 1 - blockIdx.x;   // heavy tiles first
    const int b = blockIdx.y / HH, h = blockIdx.y % HH;
    const int wm = w * 32;
    const int qlo = qt * 256 + wm;               // warp's first q row

    const int la  = lane & 7;
    const int lb8 = ((lane >> 3) & 1) * 8;
    const int lq8 = (lane >> 4) * 8;
    const uint32_t koff = (uint32_t)((la + lq8) * FH + lb8) * 2;  // B-type (K, Vt)
    const uint32_t poff = (uint32_t)((la + lb8) * FH + lq8) * 2;  // A-type (P)

    const __half* Qb  = Qg  + (long)b * SS * EE + h * DD;
    const __half* Kb  = Kg  + (long)b * SS * EE + h * DD;
    const __half* Vtb = Vtg + (long)(b * HH + h) * DD * SS;
    __half*       Ob  = Og  + (long)b * SS * EE + h * DD;

    // ---- stage Q tile (256 x 64 halves) into stage-0 area, extract frags ----
    {
        const __half* src = Qb + (long)(qt * 256 + tid) * EE;
        const uint32_t dst = smb + tid * FH * 2;
#pragma unroll
        for (int j = 0; j < 8; j++) cp_async16(dst + j * 16, src + j * 8);
        CP_COMMIT(); CP_WAIT(0);
    }
    __syncthreads();

    uint32_t qf[2][4][4];
#pragma unroll
    for (int mt = 0; mt < 2; mt++) {
        const uint32_t qoff = (uint32_t)((wm + mt * 16 + la + lb8) * FH + lq8) * 2;
#pragma unroll
        for (int ks = 0; ks < 4; ks++)
            ldsm_x4(qf[mt][ks], smb + qoff + ks * 32);
    }
    __syncthreads();

    float of[2][8][4];
#pragma unroll
    for (int mt = 0; mt < 2; mt++)
#pragma unroll
        for (int i = 0; i < 8; i++)
#pragma unroll
            for (int j = 0; j < 4; j++) of[mt][i][j] = 0.f;
    float mM[2][2], lL[2][2];
#pragma unroll
    for (int mt = 0; mt < 2; mt++) {
        mM[mt][0] = NEG_BIG; mM[mt][1] = NEG_BIG;
        lL[mt][0] = 0.f;     lL[mt][1] = 0.f;
    }

    const int lr = tid >> 2, lc = (tid & 3) * 16;
    const int ntiles = 4 * qt + 4;
    const uint32_t pbase = smb + (2 * KVBUF_H + w * 32 * FH) * 2;
    __half* Pwh = Ph + w * 32 * FH;

    // prologue: tile 0 -> stage 0
    {
        const uint32_t kdst = smb + (lr * FH + lc) * 2;
        const uint32_t vdst = smb + (KVH + lr * FH + lc) * 2;
        const __half* ksrc = Kb + (long)lr * EE + lc;
        const __half* vsrc = Vtb + (long)lr * SS + lc;
#pragma unroll
        for (int j = 0; j < 2; j++) cp_async16(kdst + j * 16, ksrc + j * 8);
#pragma unroll
        for (int j = 0; j < 2; j++) cp_async16(vdst + j * 16, vsrc + j * 8);
        CP_COMMIT();
    }

    for (int kt = 0; kt < ntiles; kt++) {
        const int cur = kt & 1, nxt = cur ^ 1;

        if (kt + 1 < ntiles) {
            const uint32_t kdst = smb + (nxt * KVBUF_H + lr * FH + lc) * 2;
            const uint32_t vdst = smb + (nxt * KVBUF_H + KVH + lr * FH + lc) * 2;
            const __half* ksrc = Kb + (long)((kt + 1) * 64 + lr) * EE + lc;
            const __half* vsrc = Vtb + (long)lr * SS + (kt + 1) * 64 + lc;
#pragma unroll
            for (int j = 0; j < 2; j++) cp_async16(kdst + j * 16, ksrc + j * 8);
#pragma unroll
            for (int j = 0; j < 2; j++) cp_async16(vdst + j * 16, vsrc + j * 8);
            CP_COMMIT();
            CP_WAIT(1);
        } else {
            CP_WAIT(0);
        }
        __syncthreads();

        const uint32_t stK = smb + cur * KVBUF_H * 2;
        const uint32_t stV = stK + KVH * 2;

        if (kt * 64 <= qlo + 31) {   // effectively kt*64 <= qlo: no fully-masked rows
            // ---- S = Q K^T (K frags shared across both m-blocks) ----
            float s[2][8][4];
#pragma unroll
            for (int mt = 0; mt < 2; mt++)
#pragma unroll
                for (int nt = 0; nt < 8; nt++)
#pragma unroll
                    for (int r = 0; r < 4; r++) s[mt][nt][r] = 0.f;
#pragma unroll
            for (int ks = 0; ks < 4; ks++) {
                uint32_t kf[8][2];
#pragma unroll
                for (int p = 0; p < 4; p++) {
                    uint32_t t4[4];
                    ldsm_x4(t4, stK + koff + p * 16 * FH * 2 + ks * 32);
                    kf[2 * p][0] = t4[0]; kf[2 * p][1] = t4[1];
                    kf[2 * p + 1][0] = t4[2]; kf[2 * p + 1][1] = t4[3];
                }
#pragma unroll
                for (int mt = 0; mt < 2; mt++)
#pragma unroll
                    for (int nt = 0; nt < 8; nt++)
                        mma_f16(s[mt][nt], qf[mt][ks], kf[nt]);
            }

            // ---- causal mask (per m-block) ----
            if (kt * 64 + 63 > qlo) {
#pragma unroll
                for (int mt = 0; mt < 2; mt++) {
                    const int r0g = qlo + mt * 16 + g, r1g = r0g + 8;
#pragma unroll
                    for (int nt = 0; nt < 8; nt++) {
                        const int col = kt * 64 + nt * 8 + 2 * tg;
                        if (col     > r0g) s[mt][nt][0] = NEG_BIG;
                        if (col + 1 > r0g) s[mt][nt][1] = NEG_BIG;
                        if (col     > r1g) s[mt][nt][2] = NEG_BIG;
                        if (col + 1 > r1g) s[mt][nt][3] = NEG_BIG;
                    }
                }
            }

            // ---- online softmax (per m-block) ----
#pragma unroll
            for (int mt = 0; mt < 2; mt++) {
                float a0 = NEG_BIG, a1 = NEG_BIG;
#pragma unroll
                for (int nt = 0; nt < 8; nt++) {
                    a0 = fmaxf(a0, fmaxf(s[mt][nt][0], s[mt][nt][1]));
                    a1 = fmaxf(a1, fmaxf(s[mt][nt][2], s[mt][nt][3]));
                }
                a0 = fmaxf(a0, __shfl_xor_sync(0xffffffffu, a0, 1));
                a0 = fmaxf(a0, __shfl_xor_sync(0xffffffffu, a0, 2));
                a1 = fmaxf(a1, __shfl_xor_sync(0xffffffffu, a1, 1));
                a1 = fmaxf(a1, __shfl_xor_sync(0xffffffffu, a1, 2));

                const float mn0 = fmaxf(mM[mt][0], a0), mn1 = fmaxf(mM[mt][1], a1);
                const float cf0 = __expf(mM[mt][0] - mn0), cf1 = __expf(mM[mt][1] - mn1);
                mM[mt][0] = mn0; mM[mt][1] = mn1;

                float sum0 = 0.f, sum1 = 0.f;
#pragma unroll
                for (int nt = 0; nt < 8; nt++) {
                    float p0 = __expf(s[mt][nt][0] - mn0);
                    float p1 = __expf(s[mt][nt][1] - mn0);
                    float p2 = __expf(s[mt][nt][2] - mn1);
                    float p3 = __expf(s[mt][nt][3] - mn1);
                    sum0 += p0 + p1; sum1 += p2 + p3;
                    *(__half2*)&Pwh[(mt * 16 + g)     * FH + nt * 8 + 2 * tg] =
                        __floats2half2_rn(p0, p1);
                    *(__half2*)&Pwh[(mt * 16 + g + 8) * FH + nt * 8 + 2 * tg] =
                        __floats2half2_rn(p2, p3);
                }
                sum0 += __shfl_xor_sync(0xffffffffu, sum0, 1);
                sum0 += __shfl_xor_sync(0xffffffffu, sum0, 2);
                sum1 += __shfl_xor_sync(0xffffffffu, sum1, 1);
                sum1 += __shfl_xor_sync(0xffffffffu, sum1, 2);
                lL[mt][0] = lL[mt][0] * cf0 + sum0;
                lL[mt][1] = lL[mt][1] * cf1 + sum1;
#pragma unroll
                for (int nt = 0; nt < 8; nt++) {
                    of[mt][nt][0] *= cf0; of[mt][nt][1] *= cf0;
                    of[mt][nt][2] *= cf1; of[mt][nt][3] *= cf1;
                }
            }
            __syncwarp();

            // ---- O += P V (V frags shared across both m-blocks) ----
#pragma unroll
            for (int ks = 0; ks < 4; ks++) {
                uint32_t af[2][4];
#pragma unroll
                for (int mt = 0; mt < 2; mt++)
                    ldsm_x4(af[mt], pbase + poff + mt * 16 * FH * 2 + ks * 32);
                uint32_t vf[8][2];
#pragma unroll
                for (int p = 0; p < 4; p++) {
                    uint32_t t4[4];
                    ldsm_x4(t4, stV + koff + p * 16 * FH * 2 + ks * 32);
                    vf[2 * p][0] = t4[0]; vf[2 * p][1] = t4[1];
                    vf[2 * p + 1][0] = t4[2]; vf[2 * p + 1][1] = t4[3];
                }
#pragma unroll
                for (int mt = 0; mt < 2; mt++)
#pragma unroll
                    for (int dn = 0; dn < 8; dn++)
                        mma_f16(of[mt][dn], af[mt], vf[dn]);
            }
        }
        __syncthreads();
    }

    // ---- epilogue: normalize, store fp16 ----
#pragma unroll
    for (int mt = 0; mt < 2; mt++) {
        const float i0 = 1.f / lL[mt][0], i1 = 1.f / lL[mt][1];
        const int r0g = qt * 256 + wm + mt * 16 + g, r1g = r0g + 8;
#pragma unroll
        for (int dn = 0; dn < 8; dn++) {
            const int col = dn * 8 + 2 * tg;
            *(__half2*)(Ob + (long)r0g * EE + col) =
                __floats2half2_rn(of[mt][dn][0] * i0, of[mt][dn][1] * i0);
            *(__half2*)(Ob + (long)r1g * EE + col) =
                __floats2half2_rn(of[mt][dn][2] * i1, of[mt][dn][3] * i1);
        }
    }
}

// ---------------------------------------------------------------------------
extern "C" void kernel_launch(void* const* d_in, const int* in_sizes, int n_in,
                              void* d_out, int out_size)
{
    const float* x  = (const float*)d_in[0];
    const float* Wq = (const float*)d_in[1];
    const float* Wk = (const float*)d_in[2];
    const float* Wv = (const float*)d_in[3];
    const float* Wo = (const float*)d_in[4];
    const float* bo = (const float*)d_in[5];
    float* out = (float*)d_out;

    __half *qh, *kh, *vt, *ah, *xh, *wqh, *wkh, *wvh, *woh;
    cudaGetSymbolAddress((void**)&qh,  g_qh);
    cudaGetSymbolAddress((void**)&kh,  g_kh);
    cudaGetSymbolAddress((void**)&vt,  g_vt);
    cudaGetSymbolAddress((void**)&ah,  g_ah);
    cudaGetSymbolAddress((void**)&xh,  g_xh);
    cudaGetSymbolAddress((void**)&wqh, g_wqh);
    cudaGetSymbolAddress((void**)&wkh, g_wkh);
    cudaGetSymbolAddress((void**)&wvh, g_wvh);
    cudaGetSymbolAddress((void**)&woh, g_woh);

    // fused prep
    const int xn4 = BSROWS * EE / 4, wn4 = EE * EE / 4;
    const int ptot = xn4 + 4 * wn4;
    prep_all<<<(ptot + 255) / 256, 256>>>(x, Wq, Wk, Wv, Wo,
                                          xh, wqh, wkh, wvh, woh, xn4, wn4);

    cudaFuncSetAttribute(gemm_qkv_h,
                         cudaFuncAttributeMaxDynamicSharedMemorySize, GEMM_SMEM);
    cudaFuncSetAttribute(gemm_h,
                         cudaFuncAttributeMaxDynamicSharedMemorySize, GEMM_SMEM);

    gemm_qkv_h<<<dim3(12, BSROWS / 128), 256, GEMM_SMEM>>>(xh, wqh, wkh, wvh, qh, kh, vt);

    const int flash_smem = FLASH_SMEMH * sizeof(__half);   // 110592 B
    cudaFuncSetAttribute(flash_h,
                         cudaFuncAttributeMaxDynamicSharedMemorySize, flash_smem);
    flash_h<<<dim3(SS / 256, BB * HH), 256, flash_smem>>>(qh, kh, vt, ah);

    gemm_h<<<dim3(4, BSROWS / 128), 256, GEMM_SMEM>>>(ah, woh, bo, out);
}

// round 16
// speedup vs baseline: 1.0067x; 1.0067x over previous
#include <cuda_runtime.h>
#include <cuda_bf16.h>
#include <cuda_fp16.h>
#include <cstdint>

#define BB 4
#define SS 2048
#define EE 1024
#define HH 16
#define DD 64
#define BSROWS (BB * SS)   // 8192

// Scratch (device globals; allocation-free per harness rules).
__device__ __half g_qh[BSROWS * EE];        // Q, fp16, pre-scaled by 1/32
__device__ __half g_kh[BSROWS * EE];        // K, fp16, row-major
__device__ __half g_vt[BSROWS * EE];        // V^T, fp16, [b][h][d][s]
__device__ __half g_ah[BSROWS * EE];        // attention out (fp16, feeds Wo)
__device__ __half g_xh[BSROWS * EE];
__device__ __half g_wqh[EE * EE];
__device__ __half g_wkh[EE * EE];
__device__ __half g_wvh[EE * EE];
__device__ __half g_woh[EE * EE];

// ---------------------------------------------------------------------------
// helpers
// ---------------------------------------------------------------------------
__device__ __forceinline__ uint32_t smem_u32(const void* p) {
    uint32_t a;
    asm("{ .reg .u64 t; cvta.to.shared.u64 t, %1; cvt.u32.u64 %0, t; }" : "=r"(a) : "l"(p));
    return a;
}
__device__ __forceinline__ void cp_async16(uint32_t dst, const void* src) {
    asm volatile("cp.async.ca.shared.global [%0], [%1], 16;" :: "r"(dst), "l"(src));
}
#define CP_COMMIT() asm volatile("cp.async.commit_group;" ::: "memory")
#define CP_WAIT(n)  asm volatile("cp.async.wait_group %0;" :: "n"(n) : "memory")

__device__ __forceinline__ void mma_f16(float* c, const uint32_t* a, const uint32_t* b) {
    asm volatile(
        "mma.sync.aligned.m16n8k16.row.col.f32.f16.f16.f32 "
        "{%0,%1,%2,%3}, {%4,%5,%6,%7}, {%8,%9}, {%0,%1,%2,%3};"
        : "+f"(c[0]), "+f"(c[1]), "+f"(c[2]), "+f"(c[3])
        : "r"(a[0]), "r"(a[1]), "r"(a[2]), "r"(a[3]), "r"(b[0]), "r"(b[1]));
}
__device__ __forceinline__ void ldsm_x4(uint32_t* r, uint32_t addr) {
    asm volatile("ldmatrix.sync.aligned.m8n8.x4.shared.b16 {%0,%1,%2,%3}, [%4];"
                 : "=r"(r[0]), "=r"(r[1]), "=r"(r[2]), "=r"(r[3]) : "r"(addr));
}

// ---------------------------------------------------------------------------
// fused prep: fp32 -> fp16 for x + 4 weights in ONE launch
// ---------------------------------------------------------------------------
__global__ void prep_all(const float* __restrict__ x,  const float* __restrict__ wq,
                         const float* __restrict__ wk, const float* __restrict__ wv,
                         const float* __restrict__ wo,
                         __half* xh, __half* wqh, __half* wkh, __half* wvh, __half* woh,
                         int xn4, int wn4)
{
    int i = blockIdx.x * blockDim.x + threadIdx.x;
    if (i >= xn4 + 4 * wn4) return;
    const float* s; __half* d; int j;
    if (i < xn4) { s = x; d = xh; j = i; }
    else {
        int t = i - xn4, sel = t / wn4; j = t - sel * wn4;
        s = (sel == 0) ? wq : (sel == 1) ? wk : (sel == 2) ? wv : wo;
        d = (sel == 0) ? wqh : (sel == 1) ? wkh : (sel == 2) ? wvh : woh;
    }
    float4 a = ((const float4*)s)[j];
    __half2* dd = (__half2*)d + 2 * j;
    dd[0] = __floats2half2_rn(a.x, a.y);
    dd[1] = __floats2half2_rn(a.z, a.w);
}

// ---------------------------------------------------------------------------
// fp16 mma.sync GEMM: CTA 128x256, 8 warps (2M x 4N), warp tile 64x64,
// BK=64, 2-stage cp.async, ldmatrix fragments — now with explicit fragment
// double-buffering (ks+1 ldsm issued before ks MMAs).
// ---------------------------------------------------------------------------
#define HST 72
#define ROWB (HST * 2)
#define GA_H (128 * HST)
#define GB_H (256 * HST)
#define GSTG_B ((GA_H + GB_H) * 2)
#define GEMM_SMEM (2 * GSTG_B)       // 110592 B
#define NCH 16

__device__ __forceinline__ void gemm_body_h(
    const __half* __restrict__ A, const __half* __restrict__ W,
    const float* __restrict__ bias, void* __restrict__ Cv,
    int brow, int bcol, uint32_t smb, int mode)
{
    const int t    = threadIdx.x;
    const int lane = t & 31;
    const int w    = t >> 5;
    const int wm   = (w & 1) * 64;
    const int wn   = (w >> 1) * 64;
    const int g    = lane >> 2;
    const int tg   = lane & 3;

    const int la  = lane & 7;
    const int lb8 = ((lane >> 3) & 1) * 8;
    const int lq8 = (lane >> 4) * 8;
    const uint32_t aoff = (uint32_t)((wm + la + lb8) * HST + lq8) * 2;
    const uint32_t boff = (uint32_t)((wn + la + lq8) * HST + lb8) * 2;

    const int sr = t >> 1;
    const int sc = (t & 1) * 32;
    const __half* Ag = A + (long)(brow + sr) * EE + sc;
    const __half* Bg = W + (long)(bcol + t) * EE;
    const uint32_t sdA = smb + (sr * HST + sc) * 2;
    const uint32_t sdB = smb + GA_H * 2 + t * ROWB;

    float acc[4][8][4];
#pragma unroll
    for (int i = 0; i < 4; i++)
#pragma unroll
        for (int j = 0; j < 8; j++)
#pragma unroll
            for (int r = 0; r < 4; r++) acc[i][j][r] = 0.f;

#pragma unroll
    for (int j = 0; j < 4; j++) cp_async16(sdA + j * 16, Ag + j * 8);
#pragma unroll
    for (int j = 0; j < 8; j++) cp_async16(sdB + j * 16, Bg + j * 8);
    CP_COMMIT();

    for (int kc = 0; kc < NCH; kc++) {
        const int cur = kc & 1, nxt = cur ^ 1;

        if (kc + 1 < NCH) {
            const int k0 = (kc + 1) * 64;
            const uint32_t bofs = nxt * GSTG_B;
#pragma unroll
            for (int j = 0; j < 4; j++) cp_async16(sdA + bofs + j * 16, Ag + k0 + j * 8);
#pragma unroll
            for (int j = 0; j < 8; j++) cp_async16(sdB + bofs + j * 16, Bg + k0 + j * 8);
            CP_COMMIT();
            CP_WAIT(1);
        } else {
            CP_WAIT(0);
        }
        __syncthreads();

        const uint32_t stA = smb + cur * GSTG_B;
        const uint32_t stB = stA + GA_H * 2;

        // fragment double buffers
        uint32_t af[2][4][4], bf[2][8][2];

        // preload ks = 0 into buffer 0
#pragma unroll
        for (int mt = 0; mt < 4; mt++)
            ldsm_x4(af[0][mt], stA + aoff + mt * 16 * ROWB);
#pragma unroll
        for (int p = 0; p < 4; p++) {
            uint32_t t4[4];
            ldsm_x4(t4, stB + boff + p * 16 * ROWB);
            bf[0][2 * p][0] = t4[0]; bf[0][2 * p][1] = t4[1];
            bf[0][2 * p + 1][0] = t4[2]; bf[0][2 * p + 1][1] = t4[3];
        }

#pragma unroll
        for (int ks = 0; ks < 4; ks++) {
            const int cb = ks & 1, nb = cb ^ 1;
            if (ks < 3) {   // prefetch ks+1 fragments before issuing ks MMAs
#pragma unroll
                for (int mt = 0; mt < 4; mt++)
                    ldsm_x4(af[nb][mt], stA + aoff + mt * 16 * ROWB + (ks + 1) * 32);
#pragma unroll
                for (int p = 0; p < 4; p++) {
                    uint32_t t4[4];
                    ldsm_x4(t4, stB + boff + p * 16 * ROWB + (ks + 1) * 32);
                    bf[nb][2 * p][0] = t4[0]; bf[nb][2 * p][1] = t4[1];
                    bf[nb][2 * p + 1][0] = t4[2]; bf[nb][2 * p + 1][1] = t4[3];
                }
            }
#pragma unroll
            for (int mt = 0; mt < 4; mt++)
#pragma unroll
                for (int nt = 0; nt < 8; nt++)
                    mma_f16(acc[mt][nt], af[cb][mt], bf[cb][nt]);
        }
        __syncthreads();
    }

    if (mode == 0) {
        float* C = (float*)Cv;
#pragma unroll
        for (int mt = 0; mt < 4; mt++)
#pragma unroll
            for (int nt = 0; nt < 8; nt++) {
                const int row = brow + wm + mt * 16 + g;
                const int col = bcol + wn + nt * 8 + 2 * tg;
                float b0 = bias ? bias[col] : 0.f;
                float b1 = bias ? bias[col + 1] : 0.f;
                *(float2*)(C + (long)row * EE + col) =
                    make_float2(acc[mt][nt][0] + b0, acc[mt][nt][1] + b1);
                *(float2*)(C + (long)(row + 8) * EE + col) =
                    make_float2(acc[mt][nt][2] + b0, acc[mt][nt][3] + b1);
            }
    } else if (mode == 3) {          // V^T: [b][h][d][s]
        __half* C = (__half*)Cv;
#pragma unroll
        for (int mt = 0; mt < 4; mt++)
#pragma unroll
            for (int nt = 0; nt < 8; nt++) {
                const int row = brow + wm + mt * 16 + g;
                const int col = bcol + wn + nt * 8 + 2 * tg;
                const int bi = row >> 11, s = row & (SS - 1);
                const int h = col >> 6, d = col & 63;
                const long base = ((long)(bi * HH + h) * DD + d) * SS + s;
                C[base]          = __float2half_rn(acc[mt][nt][0]);
                C[base + SS]     = __float2half_rn(acc[mt][nt][1]);
                C[base + 8]      = __float2half_rn(acc[mt][nt][2]);
                C[base + SS + 8] = __float2half_rn(acc[mt][nt][3]);
            }
    } else {                         // fp16 row-major (Q scaled / K)
        __half* C = (__half*)Cv;
        const float sc2 = (mode == 1) ? 0.03125f : 1.0f;
#pragma unroll
        for (int mt = 0; mt < 4; mt++)
#pragma unroll
            for (int nt = 0; nt < 8; nt++) {
                const int row = brow + wm + mt * 16 + g;
                const int col = bcol + wn + nt * 8 + 2 * tg;
                *(__half2*)(C + (long)row * EE + col) =
                    __floats2half2_rn(acc[mt][nt][0] * sc2, acc[mt][nt][1] * sc2);
                *(__half2*)(C + (long)(row + 8) * EE + col) =
                    __floats2half2_rn(acc[mt][nt][2] * sc2, acc[mt][nt][3] * sc2);
            }
    }
}

__global__ void __launch_bounds__(256)
gemm_qkv_h(const __half* __restrict__ A,
           const __half* __restrict__ Wq, const __half* __restrict__ Wk,
           const __half* __restrict__ Wv,
           __half* __restrict__ Cq, __half* __restrict__ Ck, __half* __restrict__ Cv)
{
    extern __shared__ uint32_t smw[];
    const int sel  = blockIdx.x >> 2;
    const int bcol = (blockIdx.x & 3) * 256;
    const int brow = blockIdx.y * 128;
    const __half* W = (sel == 0) ? Wq : (sel == 1) ? Wk : Wv;
    void*         C = (sel == 0) ? (void*)Cq : (sel == 1) ? (void*)Ck : (void*)Cv;
    gemm_body_h(A, W, nullptr, C, brow, bcol, smem_u32(smw), sel + 1);
}

__global__ void __launch_bounds__(256)
gemm_h(const __half* __restrict__ A, const __half* __restrict__ W,
       const float* __restrict__ bias, float* __restrict__ C)
{
    extern __shared__ uint32_t smw[];
    gemm_body_h(A, W, bias, C, blockIdx.y * 128, blockIdx.x * 256,
                smem_u32(smw), 0);
}

// ---------------------------------------------------------------------------
// fp16 tensor-core flash attention with ldmatrix (R13/R14 proven version:
// 128 q-rows, 8 warps x 16 rows, 55KB smem, 2 CTAs/SM, heavy-qt-first).
// ---------------------------------------------------------------------------
#define FH 72                                // halves per smem row
#define KVH (64 * FH)                        // halves per K (or Vt) tile
#define KVBUF_H (2 * KVH)                    // halves per stage
#define NEG_BIG (-1e30f)
#define FLASH_SMEMH (2 * KVBUF_H + 8 * 16 * FH)   // 27648 halves = 55296 B

__global__ void __launch_bounds__(256, 2)
flash_h(const __half* __restrict__ Qg, const __half* __restrict__ Kg,
        const __half* __restrict__ Vtg, __half* __restrict__ Og)
{
    extern __shared__ __half hsm[];
    __half* Ph = hsm + 2 * KVBUF_H;

    const uint32_t smb = smem_u32(hsm);
    const int tid = threadIdx.x;
    const int w = tid >> 5, lane = tid & 31;
    const int g = lane >> 2, tg = lane & 3;
    const int qt = gridDim.x - 1 - blockIdx.x;   // heavy tiles first
    const int b = blockIdx.y / HH, h = blockIdx.y % HH;
    const int wm = w * 16;
    const int qlo = qt * 128 + wm;

    const int la  = lane & 7;
    const int lb8 = ((lane >> 3) & 1) * 8;
    const int lq8 = (lane >> 4) * 8;
    const uint32_t koff = (uint32_t)((la + lq8) * FH + lb8) * 2;  // B-type (K, Vt)
    const uint32_t poff = (uint32_t)((la + lb8) * FH + lq8) * 2;  // A-type (P)

    const __half* Qb  = Qg  + (long)b * SS * EE + h * DD;
    const __half* Kb  = Kg  + (long)b * SS * EE + h * DD;
    const __half* Vtb = Vtg + (long)(b * HH + h) * DD * SS;
    __half*       Ob  = Og  + (long)b * SS * EE + h * DD;

    // ---- stage Q tile into stage-0 area, extract fragments ----
    {
        const int r = tid >> 1, c = (tid & 1) * 32;
        const __half* src = Qb + (long)(qt * 128 + r) * EE + c;
        const uint32_t dst = smb + (r * FH + c) * 2;
#pragma unroll
        for (int j = 0; j < 4; j++) cp_async16(dst + j * 16, src + j * 8);
        CP_COMMIT(); CP_WAIT(0);
    }
    __syncthreads();

    uint32_t qf[4][4];
    {
        const uint32_t qoff = (uint32_t)((wm + la + lb8) * FH + lq8) * 2;
#pragma unroll
        for (int ks = 0; ks < 4; ks++)
            ldsm_x4(qf[ks], smb + qoff + ks * 32);
    }
    __syncthreads();

    float of[8][4];
#pragma unroll
    for (int i = 0; i < 8; i++)
#pragma unroll
        for (int j = 0; j < 4; j++) of[i][j] = 0.f;
    float m0 = NEG_BIG, m1 = NEG_BIG, l0 = 0.f, l1 = 0.f;

    const int lr = tid >> 2, lc = (tid & 3) * 16;
    const int ntiles = 2 * qt + 2;
    const uint32_t pbase = smb + (2 * KVBUF_H + w * 16 * FH) * 2;
    __half* Pwh = Ph + w * 16 * FH;

    // prologue: tile 0 -> stage 0
    {
        const uint32_t kdst = smb + (lr * FH + lc) * 2;
        const uint32_t vdst = smb + (KVH + lr * FH + lc) * 2;
        const __half* ksrc = Kb + (long)lr * EE + lc;
        const __half* vsrc = Vtb + (long)lr * SS + lc;
#pragma unroll
        for (int j = 0; j < 2; j++) cp_async16(kdst + j * 16, ksrc + j * 8);
#pragma unroll
        for (int j = 0; j < 2; j++) cp_async16(vdst + j * 16, vsrc + j * 8);
        CP_COMMIT();
    }

    for (int kt = 0; kt < ntiles; kt++) {
        const int cur = kt & 1, nxt = cur ^ 1;

        if (kt + 1 < ntiles) {
            const uint32_t kdst = smb + (nxt * KVBUF_H + lr * FH + lc) * 2;
            const uint32_t vdst = smb + (nxt * KVBUF_H + KVH + lr * FH + lc) * 2;
            const __half* ksrc = Kb + (long)((kt + 1) * 64 + lr) * EE + lc;
            const __half* vsrc = Vtb + (long)lr * SS + (kt + 1) * 64 + lc;
#pragma unroll
            for (int j = 0; j < 2; j++) cp_async16(kdst + j * 16, ksrc + j * 8);
#pragma unroll
            for (int j = 0; j < 2; j++) cp_async16(vdst + j * 16, vsrc + j * 8);
            CP_COMMIT();
            CP_WAIT(1);
        } else {
            CP_WAIT(0);
        }
        __syncthreads();

        const uint32_t stK = smb + cur * KVBUF_H * 2;
        const uint32_t stV = stK + KVH * 2;

        if (kt * 64 <= qlo + 15) {
            // ---- S = Q K^T ----
            float s[8][4];
#pragma unroll
            for (int nt = 0; nt < 8; nt++)
#pragma unroll
                for (int r = 0; r < 4; r++) s[nt][r] = 0.f;
#pragma unroll
            for (int ks = 0; ks < 4; ks++) {
                uint32_t kf[8][2];
#pragma unroll
                for (int p = 0; p < 4; p++) {
                    uint32_t t4[4];
                    ldsm_x4(t4, stK + koff + p * 16 * FH * 2 + ks * 32);
                    kf[2 * p][0] = t4[0]; kf[2 * p][1] = t4[1];
                    kf[2 * p + 1][0] = t4[2]; kf[2 * p + 1][1] = t4[3];
                }
#pragma unroll
                for (int nt = 0; nt < 8; nt++)
                    mma_f16(s[nt], qf[ks], kf[nt]);
            }

            // ---- causal mask ----
            if (kt * 64 + 63 > qlo) {
                const int r0g = qlo + g, r1g = qlo + g + 8;
#pragma unroll
                for (int nt = 0; nt < 8; nt++) {
                    const int col = kt * 64 + nt * 8 + 2 * tg;
                    if (col     > r0g) s[nt][0] = NEG_BIG;
                    if (col + 1 > r0g) s[nt][1] = NEG_BIG;
                    if (col     > r1g) s[nt][2] = NEG_BIG;
                    if (col + 1 > r1g) s[nt][3] = NEG_BIG;
                }
            }

            // ---- online softmax ----
            float a0 = NEG_BIG, a1 = NEG_BIG;
#pragma unroll
            for (int nt = 0; nt < 8; nt++) {
                a0 = fmaxf(a0, fmaxf(s[nt][0], s[nt][1]));
                a1 = fmaxf(a1, fmaxf(s[nt][2], s[nt][3]));
            }
            a0 = fmaxf(a0, __shfl_xor_sync(0xffffffffu, a0, 1));
            a0 = fmaxf(a0, __shfl_xor_sync(0xffffffffu, a0, 2));
            a1 = fmaxf(a1, __shfl_xor_sync(0xffffffffu, a1, 1));
            a1 = fmaxf(a1, __shfl_xor_sync(0xffffffffu, a1, 2));

            const float mn0 = fmaxf(m0, a0), mn1 = fmaxf(m1, a1);
            const float cf0 = __expf(m0 - mn0), cf1 = __expf(m1 - mn1);
            m0 = mn0; m1 = mn1;

            float sum0 = 0.f, sum1 = 0.f;
#pragma unroll
            for (int nt = 0; nt < 8; nt++) {
                float p0 = __expf(s[nt][0] - m0);
                float p1 = __expf(s[nt][1] - m0);
                float p2 = __expf(s[nt][2] - m1);
                float p3 = __expf(s[nt][3] - m1);
                sum0 += p0 + p1; sum1 += p2 + p3;
                *(__half2*)&Pwh[g       * FH + nt * 8 + 2 * tg] = __floats2half2_rn(p0, p1);
                *(__half2*)&Pwh[(g + 8) * FH + nt * 8 + 2 * tg] = __floats2half2_rn(p2, p3);
            }
            sum0 += __shfl_xor_sync(0xffffffffu, sum0, 1);
            sum0 += __shfl_xor_sync(0xffffffffu, sum0, 2);
            sum1 += __shfl_xor_sync(0xffffffffu, sum1, 1);
            sum1 += __shfl_xor_sync(0xffffffffu, sum1, 2);
            l0 = l0 * cf0 + sum0;
            l1 = l1 * cf1 + sum1;
#pragma unroll
            for (int nt = 0; nt < 8; nt++) {
                of[nt][0] *= cf0; of[nt][1] *= cf0;
                of[nt][2] *= cf1; of[nt][3] *= cf1;
            }
            __syncwarp();

            // ---- O += P V ----
#pragma unroll
            for (int ks = 0; ks < 4; ks++) {
                uint32_t af[4];
                ldsm_x4(af, pbase + poff + ks * 32);
                uint32_t vf[8][2];
#pragma unroll
                for (int p = 0; p < 4; p++) {
                    uint32_t t4[4];
                    ldsm_x4(t4, stV + koff + p * 16 * FH * 2 + ks * 32);
                    vf[2 * p][0] = t4[0]; vf[2 * p][1] = t4[1];
                    vf[2 * p + 1][0] = t4[2]; vf[2 * p + 1][1] = t4[3];
                }
#pragma unroll
                for (int dn = 0; dn < 8; dn++)
                    mma_f16(of[dn], af, vf[dn]);
            }
        }
        __syncthreads();
    }

    // ---- epilogue: normalize, store fp16 ----
    const float i0 = 1.f / l0, i1 = 1.f / l1;
    const int r0g = qt * 128 + wm + g, r1g = r0g + 8;
#pragma unroll
    for (int dn = 0; dn < 8; dn++) {
        const int col = dn * 8 + 2 * tg;
        *(__half2*)(Ob + (long)r0g * EE + col) =
            __floats2half2_rn(of[dn][0] * i0, of[dn][1] * i0);
        *(__half2*)(Ob + (long)r1g * EE + col) =
            __floats2half2_rn(of[dn][2] * i1, of[dn][3] * i1);
    }
}

// ---------------------------------------------------------------------------
extern "C" void kernel_launch(void* const* d_in, const int* in_sizes, int n_in,
                              void* d_out, int out_size)
{
    const float* x  = (const float*)d_in[0];
    const float* Wq = (const float*)d_in[1];
    const float* Wk = (const float*)d_in[2];
    const float* Wv = (const float*)d_in[3];
    const float* Wo = (const float*)d_in[4];
    const float* bo = (const float*)d_in[5];
    float* out = (float*)d_out;

    __half *qh, *kh, *vt, *ah, *xh, *wqh, *wkh, *wvh, *woh;
    cudaGetSymbolAddress((void**)&qh,  g_qh);
    cudaGetSymbolAddress((void**)&kh,  g_kh);
    cudaGetSymbolAddress((void**)&vt,  g_vt);
    cudaGetSymbolAddress((void**)&ah,  g_ah);
    cudaGetSymbolAddress((void**)&xh,  g_xh);
    cudaGetSymbolAddress((void**)&wqh, g_wqh);
    cudaGetSymbolAddress((void**)&wkh, g_wkh);
    cudaGetSymbolAddress((void**)&wvh, g_wvh);
    cudaGetSymbolAddress((void**)&woh, g_woh);

    // fused prep
    const int xn4 = BSROWS * EE / 4, wn4 = EE * EE / 4;
    const int ptot = xn4 + 4 * wn4;
    prep_all<<<(ptot + 255) / 256, 256>>>(x, Wq, Wk, Wv, Wo,
                                          xh, wqh, wkh, wvh, woh, xn4, wn4);

    cudaFuncSetAttribute(gemm_qkv_h,
                         cudaFuncAttributeMaxDynamicSharedMemorySize, GEMM_SMEM);
    cudaFuncSetAttribute(gemm_h,
                         cudaFuncAttributeMaxDynamicSharedMemorySize, GEMM_SMEM);

    gemm_qkv_h<<<dim3(12, BSROWS / 128), 256, GEMM_SMEM>>>(xh, wqh, wkh, wvh, qh, kh, vt);

    const int flash_smem = FLASH_SMEMH * sizeof(__half);   // 55296 B
    cudaFuncSetAttribute(flash_h,
                         cudaFuncAttributeMaxDynamicSharedMemorySize, flash_smem);
    flash_h<<<dim3(SS / 128, BB * HH), 256, flash_smem>>>(qh, kh, vt, ah);

    gemm_h<<<dim3(4, BSROWS / 128), 256, GEMM_SMEM>>>(ah, woh, bo, out);
}